// round 2
// baseline (speedup 1.0000x reference)
#include <cuda_runtime.h>
#include <cuda_bf16.h>

#define N_SAMPLES 2048
#define IN_SIZE   256
#define OUT_SIZE  256
#define N_TASKS   128

#define CHUNK     16          // samples per block-chunk
#define NCHUNK    4           // grid.y; covers any n_t via stride loop
#define XSTR      20          // smem floats per i-row: 16 samples + 4 pad

__device__ int g_off[N_TASKS + 1];
__device__ int g_sidx[N_SAMPLES];

// ---------------------------------------------------------------------------
// Kernel 1: group sample indices by task (histogram -> scan -> scatter).
// Handles task_ids stored as either int32 or int64 (device-side sniff).
// ---------------------------------------------------------------------------
__global__ void group_kernel(const void* __restrict__ task_ids_raw) {
    __shared__ int cnt[N_TASKS];
    __shared__ int off[N_TASKS + 1];
    __shared__ int hi_or;
    int tid = threadIdx.x;

    const int*       p32 = (const int*)task_ids_raw;
    const long long* p64 = (const long long*)task_ids_raw;

    // dtype sniff: if int64 with small values, every odd int32 word is 0.
    if (tid == 0) hi_or = 0;
    for (int j = tid; j < N_TASKS; j += blockDim.x) cnt[j] = 0;
    __syncthreads();
    int local_or = 0;
    for (int k = 2 * tid + 1; k < N_SAMPLES; k += 2 * blockDim.x)
        local_or |= p32[k];
    if (local_or) atomicOr(&hi_or, local_or);
    __syncthreads();
    const bool is64 = (hi_or == 0);

    for (int n = tid; n < N_SAMPLES; n += blockDim.x) {
        int t = is64 ? (int)p64[n] : p32[n];
        atomicAdd(&cnt[t], 1);
    }
    __syncthreads();

    if (tid == 0) {
        int s = 0;
        for (int t = 0; t < N_TASKS; t++) { off[t] = s; s += cnt[t]; }
        off[N_TASKS] = s;
    }
    __syncthreads();

    for (int j = tid; j <= N_TASKS; j += blockDim.x) g_off[j] = off[j];
    for (int j = tid; j < N_TASKS; j += blockDim.x) cnt[j] = off[j]; // cursor
    __syncthreads();

    for (int n = tid; n < N_SAMPLES; n += blockDim.x) {
        int t = is64 ? (int)p64[n] : p32[n];
        int pos = atomicAdd(&cnt[t], 1);
        g_sidx[pos] = n;
    }
}

// ---------------------------------------------------------------------------
// Packed f32x2 helpers
// ---------------------------------------------------------------------------
__device__ __forceinline__ void fma2(unsigned long long& acc,
                                     unsigned long long xy,
                                     unsigned long long ww) {
    asm("fma.rn.f32x2 %0, %1, %2, %0;" : "+l"(acc) : "l"(xy), "l"(ww));
}
__device__ __forceinline__ unsigned long long pack2(float lo, float hi) {
    unsigned long long r;
    asm("mov.b64 %0, {%1, %2};" : "=l"(r) : "f"(lo), "f"(hi));
    return r;
}
__device__ __forceinline__ void unpack2(unsigned long long v, float& lo, float& hi) {
    asm("mov.b64 {%0, %1}, %2;" : "=f"(lo), "=f"(hi) : "l"(v));
}

// ---------------------------------------------------------------------------
// Kernel 2: per-task chunked matvec.
// Block (t, y): all 256 output cols for up to 16 samples of task t.
// Thread tid owns output column o = tid.
// ---------------------------------------------------------------------------
__global__ __launch_bounds__(OUT_SIZE, 2)
void tsl_kernel(const float* __restrict__ x,
                const float* __restrict__ W,
                float* __restrict__ out) {
    __shared__ float xs[IN_SIZE * XSTR];   // 20 KB, layout xs[i*XSTR + s]
    __shared__ int   rows_sm[CHUNK];

    const int t   = blockIdx.x;
    const int tid = threadIdx.x;
    const int start = g_off[t];
    const int n_t   = g_off[t + 1] - start;

    const float* wcol = W + (size_t)t * IN_SIZE * OUT_SIZE + tid;

    for (int base = blockIdx.y * CHUNK; base < n_t; base += NCHUNK * CHUNK) {
        const int cnt = min(CHUNK, n_t - base);

        if (tid < CHUNK)
            rows_sm[tid] = (tid < cnt) ? g_sidx[start + base + tid] : -1;
        __syncthreads();

        // Load x chunk into smem, transposed to i-major [i][s].
        {
            const int i = tid;
            #pragma unroll
            for (int s = 0; s < CHUNK; s++) {
                int r = rows_sm[s];
                xs[i * XSTR + s] = (r >= 0) ? x[(size_t)r * IN_SIZE + i] : 0.0f;
            }
        }
        __syncthreads();

        unsigned long long acc[CHUNK / 2];
        #pragma unroll
        for (int j = 0; j < CHUNK / 2; j++) acc[j] = 0ull;

        #pragma unroll 4
        for (int i = 0; i < IN_SIZE; i++) {
            float w = __ldg(wcol + (size_t)i * OUT_SIZE);
            unsigned long long ww = pack2(w, w);
            const ulonglong2* xp = (const ulonglong2*)(xs + i * XSTR);
            ulonglong2 q0 = xp[0];
            ulonglong2 q1 = xp[1];
            ulonglong2 q2 = xp[2];
            ulonglong2 q3 = xp[3];
            fma2(acc[0], q0.x, ww);
            fma2(acc[1], q0.y, ww);
            fma2(acc[2], q1.x, ww);
            fma2(acc[3], q1.y, ww);
            fma2(acc[4], q2.x, ww);
            fma2(acc[5], q2.y, ww);
            fma2(acc[6], q3.x, ww);
            fma2(acc[7], q3.y, ww);
        }

        #pragma unroll
        for (int j = 0; j < CHUNK / 2; j++) {
            float lo, hi;
            unpack2(acc[j], lo, hi);
            int s0 = 2 * j, s1 = 2 * j + 1;
            if (s0 < cnt) out[(size_t)rows_sm[s0] * OUT_SIZE + tid] = lo;
            if (s1 < cnt) out[(size_t)rows_sm[s1] * OUT_SIZE + tid] = hi;
        }
        __syncthreads();   // protect xs/rows_sm before next chunk
    }
}

// ---------------------------------------------------------------------------
extern "C" void kernel_launch(void* const* d_in, const int* in_sizes, int n_in,
                              void* d_out, int out_size) {
    // Identify inputs by element count (robust to ordering):
    //   x: 2048*256 = 524288, task_ids: 2048, W: 128*256*256 = 8388608
    const float* x   = nullptr;
    const void*  tsk = nullptr;
    const float* W   = nullptr;
    for (int i = 0; i < n_in; i++) {
        if (in_sizes[i] == N_SAMPLES * IN_SIZE)           x   = (const float*)d_in[i];
        else if (in_sizes[i] == N_SAMPLES)                tsk = d_in[i];
        else if (in_sizes[i] == N_TASKS * IN_SIZE * OUT_SIZE) W = (const float*)d_in[i];
    }
    float* out = (float*)d_out;

    group_kernel<<<1, 256>>>(tsk);
    tsl_kernel<<<dim3(N_TASKS, NCHUNK), OUT_SIZE>>>(x, W, out);
}